// round 9
// baseline (speedup 1.0000x reference)
#include <cuda_runtime.h>
#include <cstdint>

// ============================================================
// out[8192,4096] = x @ W^T + b + 2*((x @ A^T) @ B^T)
// Folded: Weff = W + 2*(B@A);  out = x @ Weff^T + b  (tf32 mma.sync)
// R9: 2 CTAs/SM (128x128 tiles, 256 thr, 3 stages) for cross-CTA
//     tensor-pipe overlap; warp tile 64x32; cvt.rna fused on x frags.
// ============================================================

#define M_DIM 8192
#define N_DIM 4096
#define K_DIM 4096

#define BM 128
#define BN 128
#define BK 32
#define STAGES 3
#define NK (K_DIM / BK)        // 128
#define NTHREADS 256

// padded smem rows: 32 tf32 + 4 pad = 36 words = 144B (16B multiple)
#define PAD_K 36
#define A_STAGE_W (BM * PAD_K)             // 4608 words
#define B_STAGE_W (BN * PAD_K)             // 4608 words
#define STAGE_W   (A_STAGE_W + B_STAGE_W)  // 9216 words = 36864 B
#define SMEM_TOTAL (STAGES * STAGE_W * 4)  // 110592 B  (x2 CTAs = 221184 <= 228KB)

// scratch (static device global — no runtime allocation)
__device__ __align__(16) float g_Weff[(size_t)N_DIM * K_DIM];

// ---------------- PTX helpers ----------------
__device__ __forceinline__ uint32_t smem_u32(const void* p) {
    uint32_t a;
    asm("{ .reg .u64 t; cvta.to.shared.u64 t, %1; cvt.u32.u64 %0, t; }" : "=r"(a) : "l"(p));
    return a;
}

#define CP_ASYNC16(dst, src) \
    asm volatile("cp.async.cg.shared.global [%0], [%1], 16;" :: "r"(dst), "l"(src) : "memory")
#define CP_COMMIT() asm volatile("cp.async.commit_group;" ::: "memory")
#define CP_WAIT(n)  asm volatile("cp.async.wait_group %0;" :: "n"(n) : "memory")

__device__ __forceinline__ uint32_t f2tf32(float v) {
    uint32_t r;
    asm("cvt.rna.tf32.f32 %0, %1;" : "=r"(r) : "f"(v));
    return r;
}

__device__ __forceinline__ void mma_tf32(float c[4], const uint32_t a[4], const uint32_t b[2]) {
    asm volatile(
        "mma.sync.aligned.m16n8k8.row.col.f32.tf32.tf32.f32 "
        "{%0,%1,%2,%3}, {%4,%5,%6,%7}, {%8,%9}, {%0,%1,%2,%3};\n"
        : "+f"(c[0]), "+f"(c[1]), "+f"(c[2]), "+f"(c[3])
        : "r"(a[0]), "r"(a[1]), "r"(a[2]), "r"(a[3]), "r"(b[0]), "r"(b[1]));
}

// ---------------- prep kernel ----------------
// Weff[o,i] = round_tf32( W[o,i] + 2 * sum_r B[o,r] * A[r,i] )
__global__ __launch_bounds__(256) void weff_kernel(const float* __restrict__ W,
                                                   const float* __restrict__ A,
                                                   const float* __restrict__ B) {
    __shared__ float As[16][256];
    int t = threadIdx.x;
    int i0 = blockIdx.x * 256;
    int o0 = blockIdx.y * 64;
#pragma unroll
    for (int r = 0; r < 16; r++)
        As[r][t] = A[r * 4096 + i0 + t];
    __syncthreads();
    for (int oo = 0; oo < 64; oo++) {
        int o = o0 + oo;
        const float* Br = B + o * 16;
        float s = 0.f;
#pragma unroll
        for (int r = 0; r < 16; r++) s += Br[r] * As[r][t];
        float v = W[((size_t)o << 12) + i0 + t] + 2.0f * s;
        g_Weff[((size_t)o << 12) + i0 + t] = __uint_as_float(f2tf32(v));
    }
}

// ---------------- main GEMM: mma.sync tf32 ----------------
// CTA 128x128x32, 8 warps in 2(M)x4(N), warp tile 64x32, 2 CTAs/SM.
// 3-stage cp.async pipeline, ONE __syncthreads per K-iteration.
__global__ __launch_bounds__(NTHREADS, 2)
void lora_gemm_kernel(const float* __restrict__ x,
                      const float* __restrict__ bias, float* __restrict__ out) {
    extern __shared__ float smem[];
    uint32_t smem_base = smem_u32(smem);

    int tid = threadIdx.x;
    int wid = tid >> 5;
    int lane = tid & 31;
    int warp_m = (wid & 1) * 64;        // 0 or 64
    int warp_n = (wid >> 1) * 32;       // 0,32,64,96

    int m0 = blockIdx.y * BM;
    int n0 = blockIdx.x * BN;

    const float* gA = x + ((size_t)m0 << 12);
    const float* gB = g_Weff + ((size_t)n0 << 12);

    // one stage: A 128 rows x 32 cols (8x16B chunks/row), B same
    auto load_stage = [&](int stage, int kt) {
        uint32_t sA = smem_base + (uint32_t)(stage * STAGE_W * 4);
        uint32_t sB = sA + A_STAGE_W * 4;
        int kbase = kt << 5;   // kt*32
#pragma unroll
        for (int i = 0; i < 4; i++) {        // A: 128*8 = 1024 chunks / 256 thr
            int ch = tid + i * NTHREADS;
            int row = ch >> 3, c = ch & 7;
            CP_ASYNC16(sA + (uint32_t)(row * PAD_K + c * 4) * 4,
                       gA + (((size_t)row) << 12) + kbase + (c << 2));
        }
#pragma unroll
        for (int i = 0; i < 4; i++) {        // B: 128*8 = 1024 chunks
            int ch = tid + i * NTHREADS;
            int row = ch >> 3, c = ch & 7;
            CP_ASYNC16(sB + (uint32_t)(row * PAD_K + c * 4) * 4,
                       gB + (((size_t)row) << 12) + kbase + (c << 2));
        }
        CP_COMMIT();
    };

    float acc[4][4][4];
#pragma unroll
    for (int mt = 0; mt < 4; mt++)
#pragma unroll
        for (int nt = 0; nt < 4; nt++)
#pragma unroll
            for (int i = 0; i < 4; i++) acc[mt][nt][i] = 0.f;

    // prologue: fill stages 0..1 (2 groups in flight)
    load_stage(0, 0);
    load_stage(1, 1);

    int lr = lane >> 2;     // 0..7
    int lc = lane & 3;      // 0..3

    const uint32_t a_off = (uint32_t)(warp_m + lr) * PAD_K + lc;   // + mt*16*PAD_K + ks*8
    const uint32_t b_off = (uint32_t)(warp_n + lr) * PAD_K + lc;   // + nt*8*PAD_K  + ks*8

#pragma unroll 3
    for (int k = 0; k < NK; k++) {
        // exactly 2 groups outstanding here -> wait for tile k
        CP_WAIT(1);
        __syncthreads();

        // prefetch tile k+2 into slot (k+2)%3 == (k-1)%3 (consumed at iter k-1;
        // the barrier above covers the WAR hazard). Uniform group count.
        if (k + 2 < NK) load_stage((k + 2) % 3, k + 2);
        else            CP_COMMIT();

        const float* As = smem + (size_t)(k % 3) * STAGE_W + a_off;
        const float* Bs = smem + (size_t)(k % 3) * STAGE_W + A_STAGE_W + b_off;

#pragma unroll
        for (int ks = 0; ks < 4; ks++) {
            int kk = ks * 8;
            uint32_t af[4][4];
            uint32_t bf[4][2];
#pragma unroll
            for (int mt = 0; mt < 4; mt++) {
                const float* p = As + mt * 16 * PAD_K + kk;
                af[mt][0] = f2tf32(p[0]);               // round x -> tf32 in-register
                af[mt][1] = f2tf32(p[8 * PAD_K]);
                af[mt][2] = f2tf32(p[4]);
                af[mt][3] = f2tf32(p[8 * PAD_K + 4]);
            }
#pragma unroll
            for (int nt = 0; nt < 4; nt++) {
                const float* p = Bs + nt * 8 * PAD_K + kk;
                bf[nt][0] = __float_as_uint(p[0]);      // Weff pre-rounded
                bf[nt][1] = __float_as_uint(p[4]);
            }
#pragma unroll
            for (int mt = 0; mt < 4; mt++)
#pragma unroll
                for (int nt = 0; nt < 4; nt++)
                    mma_tf32(acc[mt][nt], af[mt], bf[nt]);
        }
        // no trailing barrier — next iteration's top barrier covers reuse.
    }

    // epilogue: direct stores + bias. c0,c1 -> (row, 2*lc+{0,1}); c2,c3 -> row+8.
#pragma unroll
    for (int nt = 0; nt < 4; nt++) {
        int col = n0 + warp_n + nt * 8 + 2 * lc;
        float bv0 = bias[col];
        float bv1 = bias[col + 1];
#pragma unroll
        for (int mt = 0; mt < 4; mt++) {
            int row = m0 + warp_m + mt * 16 + lr;
            float2 v0 = make_float2(acc[mt][nt][0] + bv0, acc[mt][nt][1] + bv1);
            float2 v1 = make_float2(acc[mt][nt][2] + bv0, acc[mt][nt][3] + bv1);
            *reinterpret_cast<float2*>(out + (((size_t)row) << 12) + col) = v0;
            *reinterpret_cast<float2*>(out + (((size_t)(row + 8)) << 12) + col) = v1;
        }
    }
}

// ---------------- launch ----------------
extern "C" void kernel_launch(void* const* d_in, const int* in_sizes, int n_in,
                              void* d_out, int out_size) {
    const float* x = (const float*)d_in[0];   // [8192, 4096]
    const float* W = (const float*)d_in[1];   // [4096, 4096]
    const float* b = (const float*)d_in[2];   // [4096]
    const float* A = (const float*)d_in[3];   // [16, 4096]
    const float* B = (const float*)d_in[4];   // [4096, 16]
    float* out = (float*)d_out;               // [8192, 4096]

    cudaFuncSetAttribute(lora_gemm_kernel,
                         cudaFuncAttributeMaxDynamicSharedMemorySize, SMEM_TOTAL);

    // 1) Weff = round_tf32(W + 2*B@A)
    weff_kernel<<<dim3(16, 64), 256>>>(W, A, B);
    // 2) out = round_tf32(x) @ Weff^T + b
    lora_gemm_kernel<<<dim3(N_DIM / BN, M_DIM / BM), NTHREADS, SMEM_TOTAL>>>(x, b, out);
}

// round 11
// speedup vs baseline: 1.1455x; 1.1455x over previous
#include <cuda_runtime.h>
#include <cstdint>

// ============================================================
// out[8192,4096] = x @ W^T + b + 2*((x @ A^T) @ B^T)
// Folded: Weff = W + 2*(B@A);  out = x @ Weff^T + b  (tf32 mma.sync)
// R11 == R10 resubmit (infra failure):
//      R7 shape (128x256, 8 warps, warp 64x64, 4 stages, 1 barrier)
//      + ldmatrix.x4 fragment loads (4x fewer LDS instrs)
//      + cvt.rna fused on A fragments (no roundx prepass).
// ============================================================

#define M_DIM 8192
#define N_DIM 4096
#define K_DIM 4096

#define BM 128
#define BN 256
#define BK 32
#define NK (K_DIM / BK)        // 128
#define NTHREADS 256

// padded smem rows: 32 tf32 + 4 pad = 36 words = 144B (16B multiple;
// 8-row ldmatrix access at stride 144B hits all 32 banks -> conflict-free)
#define PAD_K 36
#define A_STAGE_W (BM * PAD_K)             // 4608 words
#define B_STAGE_W (BN * PAD_K)             // 9216 words
#define STAGE_W   (A_STAGE_W + B_STAGE_W)  // 13824 words = 55296 B
#define SMEM_TOTAL (4 * STAGE_W * 4)       // 221184 B

// scratch (static device global — no runtime allocation)
__device__ __align__(16) float g_Weff[(size_t)N_DIM * K_DIM];

// ---------------- PTX helpers ----------------
__device__ __forceinline__ uint32_t smem_u32(const void* p) {
    uint32_t a;
    asm("{ .reg .u64 t; cvta.to.shared.u64 t, %1; cvt.u32.u64 %0, t; }" : "=r"(a) : "l"(p));
    return a;
}

#define CP_ASYNC16(dst, src) \
    asm volatile("cp.async.cg.shared.global [%0], [%1], 16;" :: "r"(dst), "l"(src) : "memory")
#define CP_COMMIT() asm volatile("cp.async.commit_group;" ::: "memory")
#define CP_WAIT(n)  asm volatile("cp.async.wait_group %0;" :: "n"(n) : "memory")

__device__ __forceinline__ uint32_t f2tf32(float v) {
    uint32_t r;
    asm("cvt.rna.tf32.f32 %0, %1;" : "=r"(r) : "f"(v));
    return r;
}
__device__ __forceinline__ uint32_t cvt_u(uint32_t v) {
    uint32_t r;
    asm("cvt.rna.tf32.f32 %0, %1;" : "=r"(r) : "r"(v));
    return r;
}

__device__ __forceinline__ void ldsm_x4(uint32_t& r0, uint32_t& r1, uint32_t& r2, uint32_t& r3,
                                        uint32_t addr) {
    asm volatile("ldmatrix.sync.aligned.m8n8.x4.shared.b16 {%0,%1,%2,%3}, [%4];"
                 : "=r"(r0), "=r"(r1), "=r"(r2), "=r"(r3) : "r"(addr));
}

__device__ __forceinline__ void mma_tf32(float c[4], const uint32_t a[4], const uint32_t b[2]) {
    asm volatile(
        "mma.sync.aligned.m16n8k8.row.col.f32.tf32.tf32.f32 "
        "{%0,%1,%2,%3}, {%4,%5,%6,%7}, {%8,%9}, {%0,%1,%2,%3};\n"
        : "+f"(c[0]), "+f"(c[1]), "+f"(c[2]), "+f"(c[3])
        : "r"(a[0]), "r"(a[1]), "r"(a[2]), "r"(a[3]), "r"(b[0]), "r"(b[1]));
}

// ---------------- prep kernel ----------------
// Weff[o,i] = round_tf32( W[o,i] + 2 * sum_r B[o,r] * A[r,i] )
__global__ __launch_bounds__(256) void weff_kernel(const float* __restrict__ W,
                                                   const float* __restrict__ A,
                                                   const float* __restrict__ B) {
    __shared__ float As[16][256];
    int t = threadIdx.x;
    int i0 = blockIdx.x * 256;
    int o0 = blockIdx.y * 64;
#pragma unroll
    for (int r = 0; r < 16; r++)
        As[r][t] = A[r * 4096 + i0 + t];
    __syncthreads();
    for (int oo = 0; oo < 64; oo++) {
        int o = o0 + oo;
        const float* Br = B + o * 16;
        float s = 0.f;
#pragma unroll
        for (int r = 0; r < 16; r++) s += Br[r] * As[r][t];
        float v = W[((size_t)o << 12) + i0 + t] + 2.0f * s;
        g_Weff[((size_t)o << 12) + i0 + t] = __uint_as_float(f2tf32(v));
    }
}

// ---------------- main GEMM: mma.sync tf32 + ldmatrix ----------------
// CTA 128x256x32, 8 warps in 2(M)x4(N), warp tile 64x64.
// 4-stage cp.async pipeline, ONE __syncthreads per K-iteration.
__global__ __launch_bounds__(NTHREADS, 1)
void lora_gemm_kernel(const float* __restrict__ x,
                      const float* __restrict__ bias, float* __restrict__ out) {
    extern __shared__ float smem[];
    uint32_t smem_base = smem_u32(smem);

    int tid = threadIdx.x;
    int wid = tid >> 5;
    int lane = tid & 31;
    int warp_m = (wid & 1) * 64;        // 0 or 64
    int warp_n = (wid >> 1) * 64;       // 0,64,128,192

    int m0 = blockIdx.y * BM;
    int n0 = blockIdx.x * BN;

    const float* gA = x + ((size_t)m0 << 12);
    const float* gB = g_Weff + ((size_t)n0 << 12);

    // cp.async one stage: A 128 rows, B 256 rows, 8 x 16B chunks per row
    auto load_stage = [&](int stage, int kt) {
        uint32_t sA = smem_base + (uint32_t)(stage * STAGE_W * 4);
        uint32_t sB = sA + A_STAGE_W * 4;
        int kbase = kt << 5;   // kt*32
#pragma unroll
        for (int i = 0; i < 4; i++) {        // A: 128*8 = 1024 chunks / 256 thr
            int ch = tid + i * NTHREADS;
            int row = ch >> 3, c = ch & 7;
            CP_ASYNC16(sA + (uint32_t)(row * PAD_K + c * 4) * 4,
                       gA + (((size_t)row) << 12) + kbase + (c << 2));
        }
#pragma unroll
        for (int i = 0; i < 8; i++) {        // B: 256*8 = 2048 chunks
            int ch = tid + i * NTHREADS;
            int row = ch >> 3, c = ch & 7;
            CP_ASYNC16(sB + (uint32_t)(row * PAD_K + c * 4) * 4,
                       gB + (((size_t)row) << 12) + kbase + (c << 2));
        }
        CP_COMMIT();
    };

    float acc[4][8][4];
#pragma unroll
    for (int mt = 0; mt < 4; mt++)
#pragma unroll
        for (int nt = 0; nt < 8; nt++)
#pragma unroll
            for (int i = 0; i < 4; i++) acc[mt][nt][i] = 0.f;

    // prologue: fill stages 0..2 (3 groups in flight)
    load_stage(0, 0);
    load_stage(1, 1);
    load_stage(2, 2);

    // ldmatrix per-lane word offsets.
    // A x4 (one 16x8 tile -> frags a0..a3): matrix m = lane/8:
    //   row = (m&1)*8 + lane%8, col = (m>>1)*4
    const uint32_t a_lm = ((((lane >> 3) & 1) * 8 + (lane & 7)) * PAD_K
                           + ((lane >> 4) & 1) * 4);
    // B x4 (two nt tiles -> {b[nt0][0],b[nt0][1],b[nt1][0],b[nt1][1]}):
    //   n-row = (m>>1)*8 + lane%8, col = (m&1)*4
    const uint32_t b_lm = ((((lane >> 4) & 1) * 8 + (lane & 7)) * PAD_K
                           + ((lane >> 3) & 1) * 4);

    const uint32_t a_base_off = ((uint32_t)warp_m * PAD_K + a_lm) * 4;   // bytes
    const uint32_t b_base_off = (uint32_t)(A_STAGE_W + warp_n * PAD_K + b_lm) * 4;

#pragma unroll 4
    for (int k = 0; k < NK; k++) {
        // exactly 3 groups outstanding here -> wait for tile k
        CP_WAIT(2);
        __syncthreads();

        // prefetch tile k+3 into slot (k+3)&3 == (k-1)&3 (consumed at iter k-1;
        // the barrier above covers the WAR hazard). Uniform group count.
        if (k + 3 < NK) load_stage((k + 3) & 3, k + 3);
        else            CP_COMMIT();

        uint32_t stage_base = smem_base + (uint32_t)((k & 3) * STAGE_W * 4);
        uint32_t aA = stage_base + a_base_off;
        uint32_t aB = stage_base + b_base_off;

#pragma unroll
        for (int ks = 0; ks < 4; ks++) {
            uint32_t koff = (uint32_t)(ks * 8) * 4;
            uint32_t af[4][4];
            uint32_t bf[8][2];
#pragma unroll
            for (int mt = 0; mt < 4; mt++) {
                ldsm_x4(af[mt][0], af[mt][1], af[mt][2], af[mt][3],
                        aA + (uint32_t)(mt * 16 * PAD_K) * 4 + koff);
            }
#pragma unroll
            for (int ntp = 0; ntp < 4; ntp++) {
                ldsm_x4(bf[2 * ntp][0], bf[2 * ntp][1], bf[2 * ntp + 1][0], bf[2 * ntp + 1][1],
                        aB + (uint32_t)(ntp * 16 * PAD_K) * 4 + koff);
            }
            // round x fragments to tf32 (RN, unbiased); Weff is pre-rounded
#pragma unroll
            for (int mt = 0; mt < 4; mt++)
#pragma unroll
                for (int i = 0; i < 4; i++) af[mt][i] = cvt_u(af[mt][i]);

#pragma unroll
            for (int mt = 0; mt < 4; mt++)
#pragma unroll
                for (int nt = 0; nt < 8; nt++)
                    mma_tf32(acc[mt][nt], af[mt], bf[nt]);
        }
        // no trailing barrier — next iteration's top barrier covers reuse.
    }

    int lr = lane >> 2;     // 0..7
    int lc = lane & 3;      // 0..3

    // epilogue: direct stores + bias. c0,c1 -> (row, 2*lc+{0,1}); c2,c3 -> row+8.
#pragma unroll
    for (int nt = 0; nt < 8; nt++) {
        int col = n0 + warp_n + nt * 8 + 2 * lc;
        float bv0 = bias[col];
        float bv1 = bias[col + 1];
#pragma unroll
        for (int mt = 0; mt < 4; mt++) {
            int row = m0 + warp_m + mt * 16 + lr;
            float2 v0 = make_float2(acc[mt][nt][0] + bv0, acc[mt][nt][1] + bv1);
            float2 v1 = make_float2(acc[mt][nt][2] + bv0, acc[mt][nt][3] + bv1);
            *reinterpret_cast<float2*>(out + (((size_t)row) << 12) + col) = v0;
            *reinterpret_cast<float2*>(out + (((size_t)(row + 8)) << 12) + col) = v1;
        }
    }
}

// ---------------- launch ----------------
extern "C" void kernel_launch(void* const* d_in, const int* in_sizes, int n_in,
                              void* d_out, int out_size) {
    const float* x = (const float*)d_in[0];   // [8192, 4096]
    const float* W = (const float*)d_in[1];   // [4096, 4096]
    const float* b = (const float*)d_in[2];   // [4096]
    const float* A = (const float*)d_in[3];   // [16, 4096]
    const float* B = (const float*)d_in[4];   // [4096, 16]
    float* out = (float*)d_out;               // [8192, 4096]

    cudaFuncSetAttribute(lora_gemm_kernel,
                         cudaFuncAttributeMaxDynamicSharedMemorySize, SMEM_TOTAL);

    // 1) Weff = round_tf32(W + 2*B@A)
    weff_kernel<<<dim3(16, 64), 256>>>(W, A, B);
    // 2) out = round_tf32(x) @ Weff^T + b   (rounding fused on A fragments)
    lora_gemm_kernel<<<dim3(N_DIM / BN, M_DIM / BM), NTHREADS, SMEM_TOTAL>>>(x, b, out);
}

// round 12
// speedup vs baseline: 1.1536x; 1.0071x over previous
#include <cuda_runtime.h>
#include <cstdint>

// ============================================================
// out[8192,4096] = x @ W^T + b + 2*((x @ A^T) @ B^T)
// Folded: Weff = W + 2*(B@A);  out = Xr @ Weff^T + b  (tf32 mma.sync)
// R12: compose R8 + R11 — 512 threads (16 warps, 4/SMSP) for latency
//      hiding AND ldmatrix.x4 fragment feeding; roundx prepass restored
//      so the mainloop is cvt-free (register budget <= 128 @ 512 thr).
// ============================================================

#define M_DIM 8192
#define N_DIM 4096
#define K_DIM 4096

#define BM 128
#define BN 256
#define BK 32
#define NK (K_DIM / BK)        // 128
#define NTHREADS 512

// padded smem rows: 32 tf32 + 4 pad = 36 words = 144B (16B multiple;
// 8-row ldmatrix access at stride 144B hits all 32 banks -> conflict-free)
#define PAD_K 36
#define A_STAGE_W (BM * PAD_K)             // 4608 words
#define B_STAGE_W (BN * PAD_K)             // 9216 words
#define STAGE_W   (A_STAGE_W + B_STAGE_W)  // 13824 words = 55296 B
#define SMEM_TOTAL (4 * STAGE_W * 4)       // 221184 B

// scratch (static device globals — no runtime allocation)
__device__ __align__(16) float g_Weff[(size_t)N_DIM * K_DIM];
__device__ __align__(16) float g_Xr[(size_t)M_DIM * K_DIM];

// ---------------- PTX helpers ----------------
__device__ __forceinline__ uint32_t smem_u32(const void* p) {
    uint32_t a;
    asm("{ .reg .u64 t; cvta.to.shared.u64 t, %1; cvt.u32.u64 %0, t; }" : "=r"(a) : "l"(p));
    return a;
}

#define CP_ASYNC16(dst, src) \
    asm volatile("cp.async.cg.shared.global [%0], [%1], 16;" :: "r"(dst), "l"(src) : "memory")
#define CP_COMMIT() asm volatile("cp.async.commit_group;" ::: "memory")
#define CP_WAIT(n)  asm volatile("cp.async.wait_group %0;" :: "n"(n) : "memory")

__device__ __forceinline__ uint32_t f2tf32(float v) {
    uint32_t r;
    asm("cvt.rna.tf32.f32 %0, %1;" : "=r"(r) : "f"(v));
    return r;
}

__device__ __forceinline__ void ldsm_x4(uint32_t& r0, uint32_t& r1, uint32_t& r2, uint32_t& r3,
                                        uint32_t addr) {
    asm volatile("ldmatrix.sync.aligned.m8n8.x4.shared.b16 {%0,%1,%2,%3}, [%4];"
                 : "=r"(r0), "=r"(r1), "=r"(r2), "=r"(r3) : "r"(addr));
}

__device__ __forceinline__ void mma_tf32(float c[4], const uint32_t a[4], const uint32_t b[2]) {
    asm volatile(
        "mma.sync.aligned.m16n8k8.row.col.f32.tf32.tf32.f32 "
        "{%0,%1,%2,%3}, {%4,%5,%6,%7}, {%8,%9}, {%0,%1,%2,%3};\n"
        : "+f"(c[0]), "+f"(c[1]), "+f"(c[2]), "+f"(c[3])
        : "r"(a[0]), "r"(a[1]), "r"(a[2]), "r"(a[3]), "r"(b[0]), "r"(b[1]));
}

// ---------------- prep kernels ----------------

// RN-round x to tf32 scratch (keeps mainloop cvt-free; unbiased rounding)
__global__ __launch_bounds__(256) void roundx_kernel(const float4* __restrict__ x) {
    size_t i = (size_t)blockIdx.x * 256 + threadIdx.x;
    float4 v = x[i];
    float4 o;
    o.x = __uint_as_float(f2tf32(v.x));
    o.y = __uint_as_float(f2tf32(v.y));
    o.z = __uint_as_float(f2tf32(v.z));
    o.w = __uint_as_float(f2tf32(v.w));
    reinterpret_cast<float4*>(g_Xr)[i] = o;
}

// Weff[o,i] = round_tf32( W[o,i] + 2 * sum_r B[o,r] * A[r,i] )
__global__ __launch_bounds__(256) void weff_kernel(const float* __restrict__ W,
                                                   const float* __restrict__ A,
                                                   const float* __restrict__ B) {
    __shared__ float As[16][256];
    int t = threadIdx.x;
    int i0 = blockIdx.x * 256;
    int o0 = blockIdx.y * 64;
#pragma unroll
    for (int r = 0; r < 16; r++)
        As[r][t] = A[r * 4096 + i0 + t];
    __syncthreads();
    for (int oo = 0; oo < 64; oo++) {
        int o = o0 + oo;
        const float* Br = B + o * 16;
        float s = 0.f;
#pragma unroll
        for (int r = 0; r < 16; r++) s += Br[r] * As[r][t];
        float v = W[((size_t)o << 12) + i0 + t] + 2.0f * s;
        g_Weff[((size_t)o << 12) + i0 + t] = __uint_as_float(f2tf32(v));
    }
}

// ---------------- main GEMM: mma.sync tf32 + ldmatrix ----------------
// CTA 128x256x32, 16 warps in 4(M)x4(N), warp tile 32x64.
// 4-stage cp.async pipeline, ONE __syncthreads per K-iteration.
__global__ __launch_bounds__(NTHREADS, 1)
void lora_gemm_kernel(const float* __restrict__ bias, float* __restrict__ out) {
    extern __shared__ float smem[];
    uint32_t smem_base = smem_u32(smem);

    int tid = threadIdx.x;
    int wid = tid >> 5;
    int lane = tid & 31;
    int warp_m = (wid & 3) * 32;        // 0,32,64,96
    int warp_n = (wid >> 2) * 64;       // 0,64,128,192

    int m0 = blockIdx.y * BM;
    int n0 = blockIdx.x * BN;

    const float* gA = g_Xr + ((size_t)m0 << 12);
    const float* gB = g_Weff + ((size_t)n0 << 12);

    // cp.async one stage: A 128 rows, B 256 rows, 8 x 16B chunks per row
    auto load_stage = [&](int stage, int kt) {
        uint32_t sA = smem_base + (uint32_t)(stage * STAGE_W * 4);
        uint32_t sB = sA + A_STAGE_W * 4;
        int kbase = kt << 5;   // kt*32
#pragma unroll
        for (int i = 0; i < 2; i++) {        // A: 128*8 = 1024 chunks / 512 thr
            int ch = tid + i * NTHREADS;
            int row = ch >> 3, c = ch & 7;
            CP_ASYNC16(sA + (uint32_t)(row * PAD_K + c * 4) * 4,
                       gA + (((size_t)row) << 12) + kbase + (c << 2));
        }
#pragma unroll
        for (int i = 0; i < 4; i++) {        // B: 256*8 = 2048 chunks
            int ch = tid + i * NTHREADS;
            int row = ch >> 3, c = ch & 7;
            CP_ASYNC16(sB + (uint32_t)(row * PAD_K + c * 4) * 4,
                       gB + (((size_t)row) << 12) + kbase + (c << 2));
        }
        CP_COMMIT();
    };

    float acc[2][8][4];
#pragma unroll
    for (int mt = 0; mt < 2; mt++)
#pragma unroll
        for (int nt = 0; nt < 8; nt++)
#pragma unroll
            for (int i = 0; i < 4; i++) acc[mt][nt][i] = 0.f;

    // prologue: fill stages 0..2 (3 groups in flight)
    load_stage(0, 0);
    load_stage(1, 1);
    load_stage(2, 2);

    // ldmatrix per-lane word offsets.
    // A x4 (one 16x8 tile -> frags a0..a3): matrix m = lane/8:
    //   row = (m&1)*8 + lane%8, col = (m>>1)*4
    const uint32_t a_lm = ((((lane >> 3) & 1) * 8 + (lane & 7)) * PAD_K
                           + ((lane >> 4) & 1) * 4);
    // B x4 (two nt tiles -> {b[nt0][0],b[nt0][1],b[nt1][0],b[nt1][1]}):
    //   n-row = (m>>1)*8 + lane%8, col = (m&1)*4
    const uint32_t b_lm = ((((lane >> 4) & 1) * 8 + (lane & 7)) * PAD_K
                           + ((lane >> 3) & 1) * 4);

    const uint32_t a_base_off = ((uint32_t)warp_m * PAD_K + a_lm) * 4;   // bytes
    const uint32_t b_base_off = (uint32_t)(A_STAGE_W + warp_n * PAD_K + b_lm) * 4;

#pragma unroll 2
    for (int k = 0; k < NK; k++) {
        // exactly 3 groups outstanding here -> wait for tile k
        CP_WAIT(2);
        __syncthreads();

        // prefetch tile k+3 into slot (k+3)&3 == (k-1)&3 (consumed at iter k-1;
        // the barrier above covers the WAR hazard). Uniform group count.
        if (k + 3 < NK) load_stage((k + 3) & 3, k + 3);
        else            CP_COMMIT();

        uint32_t stage_base = smem_base + (uint32_t)((k & 3) * STAGE_W * 4);
        uint32_t aA = stage_base + a_base_off;
        uint32_t aB = stage_base + b_base_off;

#pragma unroll
        for (int ks = 0; ks < 4; ks++) {
            uint32_t koff = (uint32_t)(ks * 8) * 4;
            uint32_t af[2][4];
            uint32_t bf[8][2];
#pragma unroll
            for (int mt = 0; mt < 2; mt++) {
                ldsm_x4(af[mt][0], af[mt][1], af[mt][2], af[mt][3],
                        aA + (uint32_t)(mt * 16 * PAD_K) * 4 + koff);
            }
#pragma unroll
            for (int ntp = 0; ntp < 4; ntp++) {
                ldsm_x4(bf[2 * ntp][0], bf[2 * ntp][1], bf[2 * ntp + 1][0], bf[2 * ntp + 1][1],
                        aB + (uint32_t)(ntp * 16 * PAD_K) * 4 + koff);
            }
#pragma unroll
            for (int mt = 0; mt < 2; mt++)
#pragma unroll
                for (int nt = 0; nt < 8; nt++)
                    mma_tf32(acc[mt][nt], af[mt], bf[nt]);
        }
        // no trailing barrier — next iteration's top barrier covers reuse.
    }

    int lr = lane >> 2;     // 0..7
    int lc = lane & 3;      // 0..3

    // epilogue: direct stores + bias. c0,c1 -> (row, 2*lc+{0,1}); c2,c3 -> row+8.
#pragma unroll
    for (int nt = 0; nt < 8; nt++) {
        int col = n0 + warp_n + nt * 8 + 2 * lc;
        float bv0 = bias[col];
        float bv1 = bias[col + 1];
#pragma unroll
        for (int mt = 0; mt < 2; mt++) {
            int row = m0 + warp_m + mt * 16 + lr;
            float2 v0 = make_float2(acc[mt][nt][0] + bv0, acc[mt][nt][1] + bv1);
            float2 v1 = make_float2(acc[mt][nt][2] + bv0, acc[mt][nt][3] + bv1);
            *reinterpret_cast<float2*>(out + (((size_t)row) << 12) + col) = v0;
            *reinterpret_cast<float2*>(out + (((size_t)(row + 8)) << 12) + col) = v1;
        }
    }
}

// ---------------- launch ----------------
extern "C" void kernel_launch(void* const* d_in, const int* in_sizes, int n_in,
                              void* d_out, int out_size) {
    const float* x = (const float*)d_in[0];   // [8192, 4096]
    const float* W = (const float*)d_in[1];   // [4096, 4096]
    const float* b = (const float*)d_in[2];   // [4096]
    const float* A = (const float*)d_in[3];   // [16, 4096]
    const float* B = (const float*)d_in[4];   // [4096, 16]
    float* out = (float*)d_out;               // [8192, 4096]

    cudaFuncSetAttribute(lora_gemm_kernel,
                         cudaFuncAttributeMaxDynamicSharedMemorySize, SMEM_TOTAL);

    // 1) Xr = round_tf32(x)
    roundx_kernel<<<(M_DIM * (size_t)K_DIM) / 4 / 256, 256>>>(
        reinterpret_cast<const float4*>(x));
    // 2) Weff = round_tf32(W + 2*B@A)
    weff_kernel<<<dim3(16, 64), 256>>>(W, A, B);
    // 3) out = Xr @ Weff^T + b   (mma.sync tf32 + ldmatrix)
    lora_gemm_kernel<<<dim3(N_DIM / BN, M_DIM / BM), NTHREADS, SMEM_TOTAL>>>(b, out);
}

// round 14
// speedup vs baseline: 1.8920x; 1.6401x over previous
#include <cuda_runtime.h>
#include <cuda_fp16.h>
#include <cstdint>

// ============================================================
// out[8192,4096] = x @ W^T + b + 2*((x @ A^T) @ B^T)
// Folded: Weff = W + 2*(B@A);  out = Xh @ Weffh^T + b
// R14 == R13 resubmit (infra failure):
//      fp16 m16n8k16 mma.sync (fp16 mantissa == tf32 mantissa ->
//      same accuracy, half the tensor-pipe instructions).
//      256 thr / 8 warps, warp 64x64, 4 stages, ldmatrix.x4 b16.
// ============================================================

#define M_DIM 8192
#define N_DIM 4096
#define K_DIM 4096

#define BM 128
#define BN 256
#define BK 32
#define NK (K_DIM / BK)        // 128
#define NTHREADS 256

// smem rows: 32 halves (64B) + 8 pad halves = 40 halves = 80B
// (16B multiple; 8 rows at stride 80B hit 8 distinct 16B bank segments)
#define PADH 40
#define ROW_BYTES (PADH * 2)               // 80
#define A_STG_BYTES (BM * ROW_BYTES)       // 10240
#define B_STG_BYTES (BN * ROW_BYTES)       // 20480
#define STG_BYTES   (A_STG_BYTES + B_STG_BYTES)  // 30720
#define SMEM_TOTAL  (4 * STG_BYTES)        // 122880

// scratch (static device globals — no runtime allocation)
__device__ __align__(16) __half g_Weffh[(size_t)N_DIM * K_DIM];  // 32 MB
__device__ __align__(16) __half g_Xh[(size_t)M_DIM * K_DIM];     // 64 MB

// ---------------- PTX helpers ----------------
__device__ __forceinline__ uint32_t smem_u32(const void* p) {
    uint32_t a;
    asm("{ .reg .u64 t; cvta.to.shared.u64 t, %1; cvt.u32.u64 %0, t; }" : "=r"(a) : "l"(p));
    return a;
}

#define CP_ASYNC16(dst, src) \
    asm volatile("cp.async.cg.shared.global [%0], [%1], 16;" :: "r"(dst), "l"(src) : "memory")
#define CP_COMMIT() asm volatile("cp.async.commit_group;" ::: "memory")
#define CP_WAIT(n)  asm volatile("cp.async.wait_group %0;" :: "n"(n) : "memory")

__device__ __forceinline__ void ldsm_x4(uint32_t& r0, uint32_t& r1, uint32_t& r2, uint32_t& r3,
                                        uint32_t addr) {
    asm volatile("ldmatrix.sync.aligned.m8n8.x4.shared.b16 {%0,%1,%2,%3}, [%4];"
                 : "=r"(r0), "=r"(r1), "=r"(r2), "=r"(r3) : "r"(addr));
}

__device__ __forceinline__ void mma_f16(float c[4], const uint32_t a[4], const uint32_t b[2]) {
    asm volatile(
        "mma.sync.aligned.m16n8k16.row.col.f32.f16.f16.f32 "
        "{%0,%1,%2,%3}, {%4,%5,%6,%7}, {%8,%9}, {%0,%1,%2,%3};\n"
        : "+f"(c[0]), "+f"(c[1]), "+f"(c[2]), "+f"(c[3])
        : "r"(a[0]), "r"(a[1]), "r"(a[2]), "r"(a[3]), "r"(b[0]), "r"(b[1]));
}

// ---------------- prep kernels ----------------

// x -> fp16 (RN). 8 floats in, 8 halves (16B) out per thread.
__global__ __launch_bounds__(256) void roundxh_kernel(const float4* __restrict__ x) {
    size_t i = (size_t)blockIdx.x * 256 + threadIdx.x;
    float4 v0 = x[2 * i];
    float4 v1 = x[2 * i + 1];
    __half2 h0 = __floats2half2_rn(v0.x, v0.y);
    __half2 h1 = __floats2half2_rn(v0.z, v0.w);
    __half2 h2 = __floats2half2_rn(v1.x, v1.y);
    __half2 h3 = __floats2half2_rn(v1.z, v1.w);
    uint4 o;
    o.x = *reinterpret_cast<const uint32_t*>(&h0);
    o.y = *reinterpret_cast<const uint32_t*>(&h1);
    o.z = *reinterpret_cast<const uint32_t*>(&h2);
    o.w = *reinterpret_cast<const uint32_t*>(&h3);
    reinterpret_cast<uint4*>(g_Xh)[i] = o;
}

// Weffh[o,i] = f16_rn( W[o,i] + 2 * sum_r B[o,r] * A[r,i] )
__global__ __launch_bounds__(256) void weffh_kernel(const float* __restrict__ W,
                                                    const float* __restrict__ A,
                                                    const float* __restrict__ B) {
    __shared__ float As[16][256];
    int t = threadIdx.x;
    int i0 = blockIdx.x * 256;
    int o0 = blockIdx.y * 64;
#pragma unroll
    for (int r = 0; r < 16; r++)
        As[r][t] = A[r * 4096 + i0 + t];
    __syncthreads();
    for (int oo = 0; oo < 64; oo++) {
        int o = o0 + oo;
        const float* Br = B + o * 16;
        float s = 0.f;
#pragma unroll
        for (int r = 0; r < 16; r++) s += Br[r] * As[r][t];
        float v = W[((size_t)o << 12) + i0 + t] + 2.0f * s;
        g_Weffh[((size_t)o << 12) + i0 + t] = __float2half_rn(v);
    }
}

// ---------------- main GEMM: mma.sync f16 + ldmatrix ----------------
// CTA 128x256x32, 8 warps in 2(M)x4(N), warp tile 64x64.
// 4-stage cp.async pipeline, ONE __syncthreads per K-iteration.
__global__ __launch_bounds__(NTHREADS, 1)
void lora_gemm_kernel(const float* __restrict__ bias, float* __restrict__ out) {
    extern __shared__ char smem[];
    uint32_t smem_base = smem_u32(smem);

    int tid = threadIdx.x;
    int wid = tid >> 5;
    int lane = tid & 31;
    int warp_m = (wid & 1) * 64;        // 0 or 64
    int warp_n = (wid >> 1) * 64;       // 0,64,128,192

    int m0 = blockIdx.y * BM;
    int n0 = blockIdx.x * BN;

    const __half* gA = g_Xh + ((size_t)m0 << 12);
    const __half* gB = g_Weffh + ((size_t)n0 << 12);

    // cp.async one stage: rows of 32 halves in 4 x 16B chunks
    auto load_stage = [&](int stage, int kt) {
        uint32_t sA = smem_base + (uint32_t)(stage * STG_BYTES);
        uint32_t sB = sA + A_STG_BYTES;
        int kbase = kt << 5;   // kt*32 (halves)
#pragma unroll
        for (int i = 0; i < 2; i++) {        // A: 128 rows * 4 chunks = 512
            int ch = tid + i * NTHREADS;
            int row = ch >> 2, c = ch & 3;
            CP_ASYNC16(sA + (uint32_t)(row * ROW_BYTES + c * 16),
                       gA + (((size_t)row) << 12) + kbase + (c << 3));
        }
#pragma unroll
        for (int i = 0; i < 4; i++) {        // B: 256 rows * 4 chunks = 1024
            int ch = tid + i * NTHREADS;
            int row = ch >> 2, c = ch & 3;
            CP_ASYNC16(sB + (uint32_t)(row * ROW_BYTES + c * 16),
                       gB + (((size_t)row) << 12) + kbase + (c << 3));
        }
        CP_COMMIT();
    };

    float acc[4][8][4];
#pragma unroll
    for (int mt = 0; mt < 4; mt++)
#pragma unroll
        for (int nt = 0; nt < 8; nt++)
#pragma unroll
            for (int i = 0; i < 4; i++) acc[mt][nt][i] = 0.f;

    // prologue: fill stages 0..2 (3 groups in flight)
    load_stage(0, 0);
    load_stage(1, 1);
    load_stage(2, 2);

    // ldmatrix lane->address maps (byte offsets within tile).
    // A x4 -> {a0,a1,a2,a3} of one 16x16 tile:
    //   group g=lane/8: row = (g&1)*8 + lane%8, kseg = (g>>1)*8 halves
    const uint32_t a_lm = (uint32_t)((((lane >> 3) & 1) * 8 + (lane & 7)) * ROW_BYTES
                                     + ((lane >> 4) & 1) * 16);
    // B x4 -> {b0,b1} of two adjacent n8 tiles:
    //   row(n) = (g>>1)*8 + lane%8, kseg = (g&1)*8 halves
    const uint32_t b_lm = (uint32_t)((((lane >> 4) & 1) * 8 + (lane & 7)) * ROW_BYTES
                                     + ((lane >> 3) & 1) * 16);

    const uint32_t a_base_off = (uint32_t)(warp_m * ROW_BYTES) + a_lm;
    const uint32_t b_base_off = (uint32_t)(A_STG_BYTES + warp_n * ROW_BYTES) + b_lm;

#pragma unroll 4
    for (int k = 0; k < NK; k++) {
        // exactly 3 groups outstanding here -> wait for tile k
        CP_WAIT(2);
        __syncthreads();

        // prefetch tile k+3 into slot (k+3)&3 == (k-1)&3 (consumed at iter k-1;
        // the barrier above covers the WAR hazard). Uniform group count.
        if (k + 3 < NK) load_stage((k + 3) & 3, k + 3);
        else            CP_COMMIT();

        uint32_t stage_base = smem_base + (uint32_t)((k & 3) * STG_BYTES);
        uint32_t aA = stage_base + a_base_off;
        uint32_t aB = stage_base + b_base_off;

#pragma unroll
        for (int ks = 0; ks < 2; ks++) {     // K=16 per step
            uint32_t koff = (uint32_t)(ks * 32);   // 16 halves = 32B
            uint32_t af[4][4];
            uint32_t bf[8][2];
#pragma unroll
            for (int mt = 0; mt < 4; mt++) {
                ldsm_x4(af[mt][0], af[mt][1], af[mt][2], af[mt][3],
                        aA + (uint32_t)(mt * 16 * ROW_BYTES) + koff);
            }
#pragma unroll
            for (int ntp = 0; ntp < 4; ntp++) {
                ldsm_x4(bf[2 * ntp][0], bf[2 * ntp][1], bf[2 * ntp + 1][0], bf[2 * ntp + 1][1],
                        aB + (uint32_t)(ntp * 16 * ROW_BYTES) + koff);
            }
#pragma unroll
            for (int mt = 0; mt < 4; mt++)
#pragma unroll
                for (int nt = 0; nt < 8; nt++)
                    mma_f16(acc[mt][nt], af[mt], bf[nt]);
        }
        // no trailing barrier — next iteration's top barrier covers reuse.
    }

    int lr = lane >> 2;     // 0..7
    int lc = lane & 3;      // 0..3

    // epilogue: direct stores + bias. c0,c1 -> (row, 2*lc+{0,1}); c2,c3 -> row+8.
#pragma unroll
    for (int nt = 0; nt < 8; nt++) {
        int col = n0 + warp_n + nt * 8 + 2 * lc;
        float bv0 = bias[col];
        float bv1 = bias[col + 1];
#pragma unroll
        for (int mt = 0; mt < 4; mt++) {
            int row = m0 + warp_m + mt * 16 + lr;
            float2 v0 = make_float2(acc[mt][nt][0] + bv0, acc[mt][nt][1] + bv1);
            float2 v1 = make_float2(acc[mt][nt][2] + bv0, acc[mt][nt][3] + bv1);
            *reinterpret_cast<float2*>(out + (((size_t)row) << 12) + col) = v0;
            *reinterpret_cast<float2*>(out + (((size_t)(row + 8)) << 12) + col) = v1;
        }
    }
}

// ---------------- launch ----------------
extern "C" void kernel_launch(void* const* d_in, const int* in_sizes, int n_in,
                              void* d_out, int out_size) {
    const float* x = (const float*)d_in[0];   // [8192, 4096]
    const float* W = (const float*)d_in[1];   // [4096, 4096]
    const float* b = (const float*)d_in[2];   // [4096]
    const float* A = (const float*)d_in[3];   // [16, 4096]
    const float* B = (const float*)d_in[4];   // [4096, 16]
    float* out = (float*)d_out;               // [8192, 4096]

    cudaFuncSetAttribute(lora_gemm_kernel,
                         cudaFuncAttributeMaxDynamicSharedMemorySize, SMEM_TOTAL);

    // 1) Xh = f16_rn(x)     (8 floats per thread)
    roundxh_kernel<<<(M_DIM * (size_t)K_DIM) / 8 / 256, 256>>>(
        reinterpret_cast<const float4*>(x));
    // 2) Weffh = f16_rn(W + 2*B@A)
    weffh_kernel<<<dim3(16, 64), 256>>>(W, A, B);
    // 3) out = Xh @ Weffh^T + b   (mma.sync f16 m16n8k16 + ldmatrix)
    lora_gemm_kernel<<<dim3(N_DIM / BN, M_DIM / BM), NTHREADS, SMEM_TOTAL>>>(b, out);
}